// round 3
// baseline (speedup 1.0000x reference)
#include <cuda_runtime.h>

// Problem: x[4,1024,32,256] -> QKV proj -> 8-head attention over 32-token
// windows -> out proj + bias. 4096 independent groups of 32 tokens.
constexpr int TOK    = 32;
constexpr int DMODEL = 256;
constexpr int HEADS  = 8;
constexpr int DHEAD  = 64;
constexpr int INNER  = 512;
constexpr int GROUPS = 4096;
constexpr int NQKV   = 1536;

// ---- dynamic smem layout (float offsets) ----
constexpr int XS_OFF  = 0;                       // x tile [32][256], padded stride
constexpr int XS_STR  = 260;                     // 260%32=4 -> conflict-free row bcast
constexpr int WQ_OFF  = XS_OFF + 32 * XS_STR;    // W chunk stages [32][64] each
constexpr int WK_OFF  = WQ_OFF + 32 * 64;
constexpr int WV_OFF  = WK_OFF + 32 * 64;
constexpr int QKV_STR = 68;                      // 68%32=4 -> conflict-free
constexpr int QS_OFF  = WV_OFF + 32 * 64;        // Q[32][64]
constexpr int KS_OFF  = QS_OFF + 32 * QKV_STR;
constexpr int VS_OFF  = KS_OFF + 32 * QKV_STR;
constexpr int PS_STR  = 33;
constexpr int PS_OFF  = VS_OFF + 32 * QKV_STR;   // probs [32][32]
constexpr int AS_OFF  = PS_OFF + 32 * PS_STR;    // attn out [32][64]
constexpr int WO_OFF  = AS_OFF + 32 * QKV_STR;   // Wout chunk [8][256]
constexpr int SM_FLOATS = WO_OFF + 8 * 256;      // = 26272 floats
constexpr int SM_BYTES  = SM_FLOATS * 4;         // ~102.6 KB -> 2 blocks/SM

__global__ __launch_bounds__(256, 2)
void fused_attn_kernel(const float* __restrict__ x,
                       const float* __restrict__ Wqkv,
                       const float* __restrict__ Wout,
                       const float* __restrict__ bout,
                       float* __restrict__ out)
{
    extern __shared__ float sm[];
    const int tid = threadIdx.x;
    const int g   = blockIdx.x;
    const int i   = tid >> 3;       // token row 0..31 owned by this thread
    const int cb  = tid & 7;        // 8-way column split
    const int d0  = cb * 8;         // head-dim slice base for QKV/attn phases

    // ---- Phase A: load x[32][256] tile into smem (coalesced float4) ----
    {
        const float4* xg = reinterpret_cast<const float4*>(x + (size_t)g * TOK * DMODEL);
        #pragma unroll
        for (int it = 0; it < 8; it++) {
            int l = tid + it * 256;            // 0..2047 float4s
            int row = l >> 6, c4 = l & 63;
            *reinterpret_cast<float4*>(sm + XS_OFF + row * XS_STR + c4 * 4) = xg[l];
        }
    }

    // Output accumulators: thread owns row i, cols {cb*4 + q*32 : q<8} (strided
    // so the Wout smem reads hit 32 distinct banks). Bias folded in here.
    float4 o[8];
    #pragma unroll
    for (int q = 0; q < 8; q++)
        o[q] = *reinterpret_cast<const float4*>(bout + cb * 4 + q * 32);

    __syncthreads();

    for (int h = 0; h < HEADS; h++) {
        // ================= B1: Q,K,V[32][64] for head h =================
        float qa[8] = {}, ka[8] = {}, va[8] = {};
        for (int kc = 0; kc < DMODEL; kc += 32) {
            __syncthreads();   // previous chunk (or phase) fully consumed
            // stage Wq/Wk/Wv[32][64] slices for this head (coalesced)
            #pragma unroll
            for (int it = 0; it < 6; it++) {
                int l   = tid + it * 256;      // 0..1535 float4s
                int sec = l >> 9;              // 0=q 1=k 2=v
                int rem = l & 511;
                int kk  = rem >> 4, dq = rem & 15;
                float4 w = *reinterpret_cast<const float4*>(
                    Wqkv + (size_t)(kc + kk) * NQKV + sec * INNER + h * DHEAD + dq * 4);
                float* dst = sm + (sec == 0 ? WQ_OFF : sec == 1 ? WK_OFF : WV_OFF)
                           + kk * 64 + dq * 4;
                *reinterpret_cast<float4*>(dst) = w;
            }
            __syncthreads();
            #pragma unroll 8
            for (int kk = 0; kk < 32; kk++) {
                const float xv = sm[XS_OFF + i * XS_STR + kc + kk];
                const float* wq = sm + WQ_OFF + kk * 64 + d0;
                const float* wk = sm + WK_OFF + kk * 64 + d0;
                const float* wv = sm + WV_OFF + kk * 64 + d0;
                #pragma unroll
                for (int ph = 0; ph < 2; ph++) {
                    const float4 aq = *reinterpret_cast<const float4*>(wq + ph * 4);
                    const float4 ak = *reinterpret_cast<const float4*>(wk + ph * 4);
                    const float4 av = *reinterpret_cast<const float4*>(wv + ph * 4);
                    qa[ph*4+0] += xv * aq.x; qa[ph*4+1] += xv * aq.y;
                    qa[ph*4+2] += xv * aq.z; qa[ph*4+3] += xv * aq.w;
                    ka[ph*4+0] += xv * ak.x; ka[ph*4+1] += xv * ak.y;
                    ka[ph*4+2] += xv * ak.z; ka[ph*4+3] += xv * ak.w;
                    va[ph*4+0] += xv * av.x; va[ph*4+1] += xv * av.y;
                    va[ph*4+2] += xv * av.z; va[ph*4+3] += xv * av.w;
                }
            }
        }
        __syncthreads();
        *reinterpret_cast<float4*>(sm + QS_OFF + i * QKV_STR + d0)     = make_float4(qa[0], qa[1], qa[2], qa[3]);
        *reinterpret_cast<float4*>(sm + QS_OFF + i * QKV_STR + d0 + 4) = make_float4(qa[4], qa[5], qa[6], qa[7]);
        *reinterpret_cast<float4*>(sm + KS_OFF + i * QKV_STR + d0)     = make_float4(ka[0], ka[1], ka[2], ka[3]);
        *reinterpret_cast<float4*>(sm + KS_OFF + i * QKV_STR + d0 + 4) = make_float4(ka[4], ka[5], ka[6], ka[7]);
        *reinterpret_cast<float4*>(sm + VS_OFF + i * QKV_STR + d0)     = make_float4(va[0], va[1], va[2], va[3]);
        *reinterpret_cast<float4*>(sm + VS_OFF + i * QKV_STR + d0 + 4) = make_float4(va[4], va[5], va[6], va[7]);
        __syncthreads();

        // ================= B2: scores + softmax + P@V =================
        {   // thread (i, cb): scores S[i][j] for j = cb + jj*8 (bank-friendly)
            float s[4] = {};
            #pragma unroll
            for (int d4 = 0; d4 < DHEAD; d4 += 4) {
                const float4 qv = *reinterpret_cast<const float4*>(sm + QS_OFF + i * QKV_STR + d4);
                #pragma unroll
                for (int jj = 0; jj < 4; jj++) {
                    const float4 kv = *reinterpret_cast<const float4*>(
                        sm + KS_OFF + (cb + jj * 8) * QKV_STR + d4);
                    s[jj] += qv.x*kv.x + qv.y*kv.y + qv.z*kv.z + qv.w*kv.w;
                }
            }
            #pragma unroll
            for (int jj = 0; jj < 4; jj++)
                sm[PS_OFF + i * PS_STR + cb + jj * 8] = s[jj] * 0.125f;  // *DHEAD^-0.5
        }
        __syncthreads();
        if (tid < 32) {   // softmax, one thread per query row
            float* pr = sm + PS_OFF + tid * PS_STR;
            float mx = pr[0];
            #pragma unroll
            for (int j = 1; j < TOK; j++) mx = fmaxf(mx, pr[j]);
            float sum = 0.f;
            #pragma unroll
            for (int j = 0; j < TOK; j++) { float e = __expf(pr[j] - mx); pr[j] = e; sum += e; }
            const float inv = 1.f / sum;
            #pragma unroll
            for (int j = 0; j < TOK; j++) pr[j] *= inv;
        }
        __syncthreads();
        {   // A[i][d0..d0+7] = sum_j P[i][j] * V[j][d]
            float a[8] = {};
            #pragma unroll 8
            for (int j = 0; j < TOK; j++) {
                const float p = sm[PS_OFF + i * PS_STR + j];
                const float4 v0 = *reinterpret_cast<const float4*>(sm + VS_OFF + j * QKV_STR + d0);
                const float4 v1 = *reinterpret_cast<const float4*>(sm + VS_OFF + j * QKV_STR + d0 + 4);
                a[0] += p * v0.x; a[1] += p * v0.y; a[2] += p * v0.z; a[3] += p * v0.w;
                a[4] += p * v1.x; a[5] += p * v1.y; a[6] += p * v1.z; a[7] += p * v1.w;
            }
            *reinterpret_cast<float4*>(sm + AS_OFF + i * QKV_STR + d0)     = make_float4(a[0], a[1], a[2], a[3]);
            *reinterpret_cast<float4*>(sm + AS_OFF + i * QKV_STR + d0 + 4) = make_float4(a[4], a[5], a[6], a[7]);
        }
        __syncthreads();

        // ================= B3: out += A_h @ Wout[h*64 : (h+1)*64] =================
        for (int dc = 0; dc < DHEAD; dc += 8) {
            #pragma unroll
            for (int it = 0; it < 2; it++) {   // stage Wout[8][256] chunk
                int l = tid + it * 256;        // 0..511 float4s
                int dd = l >> 6, c4 = l & 63;
                *reinterpret_cast<float4*>(sm + WO_OFF + dd * 256 + c4 * 4) =
                    *reinterpret_cast<const float4*>(
                        Wout + (size_t)(h * DHEAD + dc + dd) * DMODEL + c4 * 4);
            }
            __syncthreads();
            #pragma unroll
            for (int dd = 0; dd < 8; dd++) {
                const float a = sm[AS_OFF + i * QKV_STR + dc + dd];
                #pragma unroll
                for (int q = 0; q < 8; q++) {
                    const float4 w = *reinterpret_cast<const float4*>(
                        sm + WO_OFF + dd * 256 + q * 32 + cb * 4);
                    o[q].x += a * w.x; o[q].y += a * w.y;
                    o[q].z += a * w.z; o[q].w += a * w.w;
                }
            }
            __syncthreads();
        }
    }

    // ---- store: row g*32+i, cols cb*4 + q*32 ----
    float* orow = out + ((size_t)g * TOK + i) * DMODEL;
    #pragma unroll
    for (int q = 0; q < 8; q++)
        *reinterpret_cast<float4*>(orow + cb * 4 + q * 32) = o[q];
}

extern "C" void kernel_launch(void* const* d_in, const int* in_sizes, int n_in,
                              void* d_out, int out_size)
{
    const float* x    = (const float*)d_in[0];   // [4,1024,32,256]
    const float* Wqkv = (const float*)d_in[1];   // [256,1536]
    const float* Wout = (const float*)d_in[2];   // [512,256]
    const float* bout = (const float*)d_in[3];   // [256]
    float* out = (float*)d_out;                  // [131072,256]

    cudaFuncSetAttribute(fused_attn_kernel,
                         cudaFuncAttributeMaxDynamicSharedMemorySize, SM_BYTES);
    fused_attn_kernel<<<GROUPS, 256, SM_BYTES>>>(x, Wqkv, Wout, bout, out);
}

// round 4
// speedup vs baseline: 3.0794x; 3.0794x over previous
#include <cuda_runtime.h>

// x[4,1024,32,256] -> QKV proj -> 8-head attention over 32-token windows
// -> out proj + bias. 4096 independent groups of 32 tokens, one block each.
constexpr int TOK    = 32;
constexpr int DMODEL = 256;
constexpr int HEADS  = 8;
constexpr int DHEAD  = 64;
constexpr int INNER  = 512;
constexpr int GROUPS = 4096;
constexpr int NQKV   = 1536;

// ---- dynamic smem layout (float offsets) ----
constexpr int XS_OFF  = 0;                      // x tile [32][256]
constexpr int XS_STR  = 260;
constexpr int WS_OFF  = XS_OFF + 32 * XS_STR;   // W chunk [32 k][192 cols qkv]
constexpr int QKV_STR = 68;
constexpr int QS_OFF  = WS_OFF + 32 * 192;      // Q [32][64] (stride 68)
constexpr int KS_OFF  = QS_OFF + 32 * QKV_STR;
constexpr int VS_OFF  = KS_OFF + 32 * QKV_STR;
constexpr int PS_STR  = 33;
constexpr int PS_OFF  = VS_OFF + 32 * QKV_STR;  // probs [32][32]
constexpr int AS_OFF  = PS_OFF + 32 * PS_STR;   // attn out [32][64]
constexpr int WO_OFF  = AS_OFF + 32 * QKV_STR;  // Wout chunk [8][256]
constexpr int SM_FLOATS = WO_OFF + 8 * 256;     // 26272 floats
constexpr int SM_BYTES  = SM_FLOATS * 4;        // ~105 KB -> 2 blocks/SM

__global__ __launch_bounds__(256, 2)
void fused_attn_kernel(const float* __restrict__ x,
                       const float* __restrict__ Wqkv,
                       const float* __restrict__ Wout,
                       const float* __restrict__ bout,
                       float* __restrict__ out)
{
    extern __shared__ float sm[];
    const int tid  = threadIdx.x;
    const int g    = blockIdx.x;
    // GEMM mapping: 8 row-threads x 32 col-threads, 4-row microtiles
    const int trow = tid >> 5;          // 0..7 -> rows trow*4 .. +3
    const int tcol = tid & 31;          // 0..31
    // attention mapping
    const int i8   = tid >> 3;          // query row 0..31
    const int cb   = tid & 7;           // 8-way split
    const int d0   = cb * 8;

    // ---- load x[32][256] tile ----
    {
        const float4* xg = reinterpret_cast<const float4*>(x + (size_t)g * TOK * DMODEL);
        #pragma unroll
        for (int it = 0; it < 8; it++) {
            int l = tid + it * 256;
            int row = l >> 6, c4 = l & 63;
            *reinterpret_cast<float4*>(sm + XS_OFF + row * XS_STR + c4 * 4) = xg[l];
        }
    }

    // Output accumulators: rows trow*4+rr, cols tcol*8 .. +7. Bias folded in.
    float o[4][8];
    {
        float bb[8];
        *reinterpret_cast<float4*>(&bb[0]) = *reinterpret_cast<const float4*>(bout + tcol * 8);
        *reinterpret_cast<float4*>(&bb[4]) = *reinterpret_cast<const float4*>(bout + tcol * 8 + 4);
        #pragma unroll
        for (int rr = 0; rr < 4; rr++)
            #pragma unroll
            for (int c = 0; c < 8; c++) o[rr][c] = bb[c];
    }
    __syncthreads();

    for (int h = 0; h < HEADS; h++) {
        // ========== B1: Q,K,V[32][64] for head h (4x2-per-matrix microtile) ==========
        float acc[3][4][2] = {};
        for (int kc = 0; kc < DMODEL; kc += 32) {
            __syncthreads();
            // stage W chunk [32 k][192 qkv-cols], coalesced
            #pragma unroll
            for (int it = 0; it < 6; it++) {
                int l  = tid + it * 256;        // 0..1535 float4s
                int kk = l / 48, c4 = l % 48;
                int col = c4 * 4;
                int sec = col >> 6, d = col & 63;
                float4 w = *reinterpret_cast<const float4*>(
                    Wqkv + (size_t)(kc + kk) * NQKV + sec * INNER + h * DHEAD + d);
                *reinterpret_cast<float4*>(sm + WS_OFF + kk * 192 + col) = w;
            }
            __syncthreads();
            #pragma unroll
            for (int kk4 = 0; kk4 < 32; kk4 += 4) {
                float a[4][4];
                #pragma unroll
                for (int rr = 0; rr < 4; rr++)
                    *reinterpret_cast<float4*>(a[rr]) = *reinterpret_cast<const float4*>(
                        sm + XS_OFF + (trow * 4 + rr) * XS_STR + kc + kk4);
                #pragma unroll
                for (int u = 0; u < 4; u++) {
                    const float* wrow = sm + WS_OFF + (kk4 + u) * 192 + 2 * tcol;
                    float2 wm[3];
                    wm[0] = *reinterpret_cast<const float2*>(wrow);
                    wm[1] = *reinterpret_cast<const float2*>(wrow + 64);
                    wm[2] = *reinterpret_cast<const float2*>(wrow + 128);
                    #pragma unroll
                    for (int m = 0; m < 3; m++)
                        #pragma unroll
                        for (int rr = 0; rr < 4; rr++) {
                            acc[m][rr][0] = fmaf(a[rr][u], wm[m].x, acc[m][rr][0]);
                            acc[m][rr][1] = fmaf(a[rr][u], wm[m].y, acc[m][rr][1]);
                        }
                }
            }
        }
        // write Q/K/V (prior readers of these regions are behind >=2 syncs)
        #pragma unroll
        for (int rr = 0; rr < 4; rr++) {
            const int row = trow * 4 + rr;
            *reinterpret_cast<float2*>(sm + QS_OFF + row * QKV_STR + 2 * tcol) =
                make_float2(acc[0][rr][0], acc[0][rr][1]);
            *reinterpret_cast<float2*>(sm + KS_OFF + row * QKV_STR + 2 * tcol) =
                make_float2(acc[1][rr][0], acc[1][rr][1]);
            *reinterpret_cast<float2*>(sm + VS_OFF + row * QKV_STR + 2 * tcol) =
                make_float2(acc[2][rr][0], acc[2][rr][1]);
        }
        __syncthreads();

        // ========== B2: scores + register softmax + P@V ==========
        {
            float s[4] = {};
            #pragma unroll
            for (int d4 = 0; d4 < DHEAD; d4 += 4) {
                const float4 qv = *reinterpret_cast<const float4*>(sm + QS_OFF + i8 * QKV_STR + d4);
                #pragma unroll
                for (int jj = 0; jj < 4; jj++) {
                    const float4 kv = *reinterpret_cast<const float4*>(
                        sm + KS_OFF + (cb + jj * 8) * QKV_STR + d4);
                    s[jj] += qv.x * kv.x + qv.y * kv.y + qv.z * kv.z + qv.w * kv.w;
                }
            }
            #pragma unroll
            for (int jj = 0; jj < 4; jj++) s[jj] *= 0.125f;   // DHEAD^-0.5
            // softmax over 32 j's: 4 local + 8 lanes (cb) via shfl
            float mx = fmaxf(fmaxf(s[0], s[1]), fmaxf(s[2], s[3]));
            #pragma unroll
            for (int msk = 1; msk < 8; msk <<= 1)
                mx = fmaxf(mx, __shfl_xor_sync(0xffffffffu, mx, msk));
            float sum = 0.f;
            #pragma unroll
            for (int jj = 0; jj < 4; jj++) { s[jj] = __expf(s[jj] - mx); sum += s[jj]; }
            #pragma unroll
            for (int msk = 1; msk < 8; msk <<= 1)
                sum += __shfl_xor_sync(0xffffffffu, sum, msk);
            const float inv = 1.f / sum;
            #pragma unroll
            for (int jj = 0; jj < 4; jj++)
                sm[PS_OFF + i8 * PS_STR + cb + jj * 8] = s[jj] * inv;
        }
        __syncthreads();
        {   // A[i8][d0..d0+7] = sum_j P[i8][j] * V[j][:]
            float a[8] = {};
            #pragma unroll 8
            for (int j = 0; j < TOK; j++) {
                const float p = sm[PS_OFF + i8 * PS_STR + j];
                const float4 v0 = *reinterpret_cast<const float4*>(sm + VS_OFF + j * QKV_STR + d0);
                const float4 v1 = *reinterpret_cast<const float4*>(sm + VS_OFF + j * QKV_STR + d0 + 4);
                a[0] = fmaf(p, v0.x, a[0]); a[1] = fmaf(p, v0.y, a[1]);
                a[2] = fmaf(p, v0.z, a[2]); a[3] = fmaf(p, v0.w, a[3]);
                a[4] = fmaf(p, v1.x, a[4]); a[5] = fmaf(p, v1.y, a[5]);
                a[6] = fmaf(p, v1.z, a[6]); a[7] = fmaf(p, v1.w, a[7]);
            }
            *reinterpret_cast<float4*>(sm + AS_OFF + i8 * QKV_STR + d0)     = *reinterpret_cast<float4*>(&a[0]);
            *reinterpret_cast<float4*>(sm + AS_OFF + i8 * QKV_STR + d0 + 4) = *reinterpret_cast<float4*>(&a[4]);
        }

        // ========== B3: out += A_h @ Wout[h*64:(h+1)*64]  (4x8 microtile) ==========
        for (int dc = 0; dc < DHEAD; dc += 8) {
            __syncthreads();   // prior chunk consumed (and A writes visible on first pass)
            #pragma unroll
            for (int it = 0; it < 2; it++) {
                int l = tid + it * 256;
                int dd = l >> 6, c4 = l & 63;
                *reinterpret_cast<float4*>(sm + WO_OFF + dd * 256 + c4 * 4) =
                    *reinterpret_cast<const float4*>(
                        Wout + (size_t)(h * DHEAD + dc + dd) * DMODEL + c4 * 4);
            }
            __syncthreads();
            #pragma unroll
            for (int dd = 0; dd < 8; dd++) {
                float av[4];
                #pragma unroll
                for (int rr = 0; rr < 4; rr++)
                    av[rr] = sm[AS_OFF + (trow * 4 + rr) * QKV_STR + dc + dd];
                float w[8];
                *reinterpret_cast<float4*>(&w[0]) =
                    *reinterpret_cast<const float4*>(sm + WO_OFF + dd * 256 + tcol * 8);
                *reinterpret_cast<float4*>(&w[4]) =
                    *reinterpret_cast<const float4*>(sm + WO_OFF + dd * 256 + tcol * 8 + 4);
                #pragma unroll
                for (int rr = 0; rr < 4; rr++)
                    #pragma unroll
                    for (int c = 0; c < 8; c++)
                        o[rr][c] = fmaf(av[rr], w[c], o[rr][c]);
            }
        }
        __syncthreads();
    }

    // ---- store: rows g*32 + trow*4+rr, cols tcol*8 .. +7 ----
    #pragma unroll
    for (int rr = 0; rr < 4; rr++) {
        float* orow = out + ((size_t)g * TOK + trow * 4 + rr) * DMODEL + tcol * 8;
        *reinterpret_cast<float4*>(orow)     = *reinterpret_cast<float4*>(&o[rr][0]);
        *reinterpret_cast<float4*>(orow + 4) = *reinterpret_cast<float4*>(&o[rr][4]);
    }
}

extern "C" void kernel_launch(void* const* d_in, const int* in_sizes, int n_in,
                              void* d_out, int out_size)
{
    const float* x    = (const float*)d_in[0];   // [4,1024,32,256]
    const float* Wqkv = (const float*)d_in[1];   // [256,1536]
    const float* Wout = (const float*)d_in[2];   // [512,256]
    const float* bout = (const float*)d_in[3];   // [256]
    float* out = (float*)d_out;                  // [131072,256]

    cudaFuncSetAttribute(fused_attn_kernel,
                         cudaFuncAttributeMaxDynamicSharedMemorySize, SM_BYTES);
    fused_attn_kernel<<<GROUPS, 256, SM_BYTES>>>(x, Wqkv, Wout, bout, out);
}

// round 5
// speedup vs baseline: 8.8866x; 2.8858x over previous
#include <cuda_runtime.h>
#include <cstdint>

constexpr int TOK = 32, DMODEL = 256, HEADS = 8, INNER = 512;
constexpr int GROUPS = 4096, NQKV = 1536, DHEAD = 64;

// ---- smem plan (float offsets). Strides chosen for conflict-free MMA
// fragment loads: A-side arrays stride%32==4, B-side arrays stride%32==8.
constexpr int XS_STR = 260, XS_OFF = 0;                   // x  tf32 [32][256]
constexpr int WS_STR = 200, WS_OFF = XS_OFF + 32 * XS_STR;// Wqkv chunk tf32 [32][192]
constexpr int PS_STR = 36,  PS_OFF = WS_OFF;              // (alias) probs tf32 [32][32]
constexpr int AS_STR = 68,  AS_OFF = WS_OFF + 1216;       // (alias) attn-out tf32 [32][64]
constexpr int QS_STR = 68,  QS_OFF = WS_OFF + 32 * WS_STR;// Q tf32 [32][64]
constexpr int KS_STR = 68,  KS_OFF = QS_OFF + 32 * QS_STR;// K tf32 [32][64]
constexpr int VS_STR = 72,  VS_OFF = KS_OFF + 32 * KS_STR;// V tf32 [32][64]
constexpr int WO_STR = 264, WO_OFF = VS_OFF + 32 * VS_STR;// Wout chunk tf32 [16][256]
constexpr int SM_FLOATS = WO_OFF + 16 * WO_STR;           // 25600 floats = 100 KB
constexpr int SM_BYTES  = SM_FLOATS * 4;

__device__ __forceinline__ float ftf(float f) {
    uint32_t u; asm("cvt.rna.tf32.f32 %0, %1;" : "=r"(u) : "f"(f));
    return __uint_as_float(u);
}
__device__ __forceinline__ void mma8(float* d, const uint32_t* a, const uint32_t* b) {
    asm volatile("mma.sync.aligned.m16n8k8.row.col.f32.tf32.tf32.f32 "
                 "{%0,%1,%2,%3},{%4,%5,%6,%7},{%8,%9},{%0,%1,%2,%3};"
                 : "+f"(d[0]), "+f"(d[1]), "+f"(d[2]), "+f"(d[3])
                 : "r"(a[0]), "r"(a[1]), "r"(a[2]), "r"(a[3]), "r"(b[0]), "r"(b[1]));
}

__global__ __launch_bounds__(256, 2)
void fused_attn_kernel(const float* __restrict__ x,
                       const float* __restrict__ Wqkv,
                       const float* __restrict__ Wout,
                       const float* __restrict__ bout,
                       float* __restrict__ out)
{
    extern __shared__ float sm[];
    const int tid = threadIdx.x;
    const int g   = blockIdx.x;
    const int w   = tid >> 5;        // warp 0..7
    const int ln  = tid & 31;
    const int g4  = ln >> 2;         // mma groupID 0..7
    const int t4  = ln & 3;          // mma tid-in-group 0..3

    // ---- stage x[32][256] as tf32 ----
    {
        const float4* xg = reinterpret_cast<const float4*>(x + (size_t)g * TOK * DMODEL);
        #pragma unroll
        for (int it = 0; it < 8; it++) {
            int l = tid + it * 256;
            int row = l >> 6, c4 = l & 63;
            float4 v = xg[l];
            *reinterpret_cast<float4*>(sm + XS_OFF + row * XS_STR + c4 * 4) =
                make_float4(ftf(v.x), ftf(v.y), ftf(v.z), ftf(v.w));
        }
    }

    // ---- out-proj accumulators, bias preloaded ----
    // o[mt][nt][4]: rows {mt*16+g4, +8}, cols {w*32+nt*8+2*t4, +1}
    float o[2][4][4];
    #pragma unroll
    for (int nt = 0; nt < 4; nt++) {
        float b0 = bout[w * 32 + nt * 8 + 2 * t4];
        float b1 = bout[w * 32 + nt * 8 + 2 * t4 + 1];
        #pragma unroll
        for (int mt = 0; mt < 2; mt++) {
            o[mt][nt][0] = b0; o[mt][nt][1] = b1;
            o[mt][nt][2] = b0; o[mt][nt][3] = b1;
        }
    }
    __syncthreads();

    for (int h = 0; h < HEADS; h++) {
        // ========== B1: QKV for head h. Warp w owns q/k/v cols [w*8, w*8+8) ==========
        float d1[3][2][4] = {};   // [matrix q/k/v][mt][4]
        for (int kc = 0; kc < DMODEL; kc += 32) {
            __syncthreads();
            #pragma unroll
            for (int it = 0; it < 6; it++) {          // stage WS [32k][192] tf32
                int l = tid + it * 256;               // 1536 float4s
                int kk = l / 48, c4 = l % 48;
                int col = c4 * 4, sec = col >> 6, dd = col & 63;
                float4 wv = *reinterpret_cast<const float4*>(
                    Wqkv + (size_t)(kc + kk) * NQKV + sec * INNER + h * DHEAD + dd);
                *reinterpret_cast<float4*>(sm + WS_OFF + kk * WS_STR + col) =
                    make_float4(ftf(wv.x), ftf(wv.y), ftf(wv.z), ftf(wv.w));
            }
            __syncthreads();
            #pragma unroll
            for (int ks = 0; ks < 4; ks++) {
                const int kb = kc + ks * 8;           // abs col in XS
                const int kl = ks * 8;                // row in WS chunk
                uint32_t a[2][4];
                #pragma unroll
                for (int mt = 0; mt < 2; mt++) {
                    int r0 = mt * 16 + g4;
                    a[mt][0] = __float_as_uint(sm[XS_OFF + r0 * XS_STR + kb + t4]);
                    a[mt][1] = __float_as_uint(sm[XS_OFF + (r0 + 8) * XS_STR + kb + t4]);
                    a[mt][2] = __float_as_uint(sm[XS_OFF + r0 * XS_STR + kb + t4 + 4]);
                    a[mt][3] = __float_as_uint(sm[XS_OFF + (r0 + 8) * XS_STR + kb + t4 + 4]);
                }
                #pragma unroll
                for (int m = 0; m < 3; m++) {
                    uint32_t b[2];
                    const int nb = m * 64 + w * 8 + g4;
                    b[0] = __float_as_uint(sm[WS_OFF + (kl + t4) * WS_STR + nb]);
                    b[1] = __float_as_uint(sm[WS_OFF + (kl + t4 + 4) * WS_STR + nb]);
                    mma8(d1[m][0], a[0], b);
                    mma8(d1[m][1], a[1], b);
                }
            }
        }
        // write Q/K/V (tf32)
        {
            const int c = w * 8 + 2 * t4;
            #pragma unroll
            for (int m = 0; m < 3; m++) {
                float* dst = sm + (m == 0 ? QS_OFF : m == 1 ? KS_OFF : VS_OFF);
                const int str = (m == 2) ? VS_STR : QS_STR;
                #pragma unroll
                for (int mt = 0; mt < 2; mt++) {
                    int r0 = mt * 16 + g4;
                    dst[r0 * str + c]           = ftf(d1[m][mt][0]);
                    dst[r0 * str + c + 1]       = ftf(d1[m][mt][1]);
                    dst[(r0 + 8) * str + c]     = ftf(d1[m][mt][2]);
                    dst[(r0 + 8) * str + c + 1] = ftf(d1[m][mt][3]);
                }
            }
        }
        __syncthreads();

        // ========== B2a: S = Q K^T * scale. Warp w -> tile (mt=w>>2, nt=w&3) ==========
        {
            const int mt = w >> 2, nt = w & 3;
            float s[4] = {};
            #pragma unroll
            for (int ks = 0; ks < 8; ks++) {
                const int kb = ks * 8;
                uint32_t a[4], b[2];
                int r0 = mt * 16 + g4;
                a[0] = __float_as_uint(sm[QS_OFF + r0 * QS_STR + kb + t4]);
                a[1] = __float_as_uint(sm[QS_OFF + (r0 + 8) * QS_STR + kb + t4]);
                a[2] = __float_as_uint(sm[QS_OFF + r0 * QS_STR + kb + t4 + 4]);
                a[3] = __float_as_uint(sm[QS_OFF + (r0 + 8) * QS_STR + kb + t4 + 4]);
                b[0] = __float_as_uint(sm[KS_OFF + (nt * 8 + g4) * KS_STR + kb + t4]);
                b[1] = __float_as_uint(sm[KS_OFF + (nt * 8 + g4) * KS_STR + kb + t4 + 4]);
                mma8(s, a, b);
            }
            const int r0 = mt * 16 + g4, c = nt * 8 + 2 * t4;
            sm[PS_OFF + r0 * PS_STR + c]           = s[0] * 0.125f;
            sm[PS_OFF + r0 * PS_STR + c + 1]       = s[1] * 0.125f;
            sm[PS_OFF + (r0 + 8) * PS_STR + c]     = s[2] * 0.125f;
            sm[PS_OFF + (r0 + 8) * PS_STR + c + 1] = s[3] * 0.125f;
        }
        __syncthreads();

        // ========== B2b: softmax rows (thread (i8,cb) owns 4 cols) ==========
        {
            const int i8 = tid >> 3, cb = tid & 7;
            float sv[4];
            #pragma unroll
            for (int jj = 0; jj < 4; jj++) sv[jj] = sm[PS_OFF + i8 * PS_STR + cb + jj * 8];
            float mx = fmaxf(fmaxf(sv[0], sv[1]), fmaxf(sv[2], sv[3]));
            #pragma unroll
            for (int msk = 1; msk < 8; msk <<= 1)
                mx = fmaxf(mx, __shfl_xor_sync(0xffffffffu, mx, msk));
            float sum = 0.f;
            #pragma unroll
            for (int jj = 0; jj < 4; jj++) { sv[jj] = __expf(sv[jj] - mx); sum += sv[jj]; }
            #pragma unroll
            for (int msk = 1; msk < 8; msk <<= 1)
                sum += __shfl_xor_sync(0xffffffffu, sum, msk);
            const float inv = 1.f / sum;
            #pragma unroll
            for (int jj = 0; jj < 4; jj++)
                sm[PS_OFF + i8 * PS_STR + cb + jj * 8] = ftf(sv[jj] * inv);
        }
        __syncthreads();

        // ========== B2c: A = P V. Warp w owns d-cols [w*8, w*8+8) ==========
        {
            float dpv[2][4] = {};
            #pragma unroll
            for (int ks = 0; ks < 4; ks++) {
                const int kb = ks * 8;
                uint32_t b[2];
                b[0] = __float_as_uint(sm[VS_OFF + (kb + t4) * VS_STR + w * 8 + g4]);
                b[1] = __float_as_uint(sm[VS_OFF + (kb + t4 + 4) * VS_STR + w * 8 + g4]);
                #pragma unroll
                for (int mt = 0; mt < 2; mt++) {
                    uint32_t a[4];
                    int r0 = mt * 16 + g4;
                    a[0] = __float_as_uint(sm[PS_OFF + r0 * PS_STR + kb + t4]);
                    a[1] = __float_as_uint(sm[PS_OFF + (r0 + 8) * PS_STR + kb + t4]);
                    a[2] = __float_as_uint(sm[PS_OFF + r0 * PS_STR + kb + t4 + 4]);
                    a[3] = __float_as_uint(sm[PS_OFF + (r0 + 8) * PS_STR + kb + t4 + 4]);
                    mma8(dpv[mt], a, b);
                }
            }
            const int c = w * 8 + 2 * t4;
            #pragma unroll
            for (int mt = 0; mt < 2; mt++) {
                int r0 = mt * 16 + g4;
                sm[AS_OFF + r0 * AS_STR + c]           = ftf(dpv[mt][0]);
                sm[AS_OFF + r0 * AS_STR + c + 1]       = ftf(dpv[mt][1]);
                sm[AS_OFF + (r0 + 8) * AS_STR + c]     = ftf(dpv[mt][2]);
                sm[AS_OFF + (r0 + 8) * AS_STR + c + 1] = ftf(dpv[mt][3]);
            }
        }
        __syncthreads();

        // ========== B3: out += A_h @ Wout[h*64:(h+1)*64]. Warp w: n [w*32,w*32+32) ==========
        #pragma unroll 1
        for (int dc = 0; dc < DHEAD; dc += 16) {
            if (dc) __syncthreads();
            #pragma unroll
            for (int it = 0; it < 4; it++) {          // stage WO [16][256] tf32
                int l = tid + it * 256;               // 1024 float4s
                int dd = l >> 6, c4 = l & 63;
                float4 wv = *reinterpret_cast<const float4*>(
                    Wout + (size_t)(h * DHEAD + dc + dd) * DMODEL + c4 * 4);
                *reinterpret_cast<float4*>(sm + WO_OFF + dd * WO_STR + c4 * 4) =
                    make_float4(ftf(wv.x), ftf(wv.y), ftf(wv.z), ftf(wv.w));
            }
            __syncthreads();
            #pragma unroll
            for (int ks = 0; ks < 2; ks++) {
                const int kb = dc + ks * 8;           // col in AS
                const int kl = ks * 8;                // row in WO chunk
                uint32_t a[2][4];
                #pragma unroll
                for (int mt = 0; mt < 2; mt++) {
                    int r0 = mt * 16 + g4;
                    a[mt][0] = __float_as_uint(sm[AS_OFF + r0 * AS_STR + kb + t4]);
                    a[mt][1] = __float_as_uint(sm[AS_OFF + (r0 + 8) * AS_STR + kb + t4]);
                    a[mt][2] = __float_as_uint(sm[AS_OFF + r0 * AS_STR + kb + t4 + 4]);
                    a[mt][3] = __float_as_uint(sm[AS_OFF + (r0 + 8) * AS_STR + kb + t4 + 4]);
                }
                #pragma unroll
                for (int nt = 0; nt < 4; nt++) {
                    uint32_t b[2];
                    const int n = w * 32 + nt * 8 + g4;
                    b[0] = __float_as_uint(sm[WO_OFF + (kl + t4) * WO_STR + n]);
                    b[1] = __float_as_uint(sm[WO_OFF + (kl + t4 + 4) * WO_STR + n]);
                    mma8(o[0][nt], a[0], b);
                    mma8(o[1][nt], a[1], b);
                }
            }
        }
        __syncthreads();
    }

    // ---- store ----
    #pragma unroll
    for (int mt = 0; mt < 2; mt++)
        #pragma unroll
        for (int nt = 0; nt < 4; nt++) {
            const int r0 = mt * 16 + g4, c = w * 32 + nt * 8 + 2 * t4;
            float* p0 = out + ((size_t)g * TOK + r0) * DMODEL + c;
            float* p1 = out + ((size_t)g * TOK + r0 + 8) * DMODEL + c;
            *reinterpret_cast<float2*>(p0) = make_float2(o[mt][nt][0], o[mt][nt][1]);
            *reinterpret_cast<float2*>(p1) = make_float2(o[mt][nt][2], o[mt][nt][3]);
        }
}

extern "C" void kernel_launch(void* const* d_in, const int* in_sizes, int n_in,
                              void* d_out, int out_size)
{
    const float* x    = (const float*)d_in[0];   // [4,1024,32,256]
    const float* Wqkv = (const float*)d_in[1];   // [256,1536]
    const float* Wout = (const float*)d_in[2];   // [512,256]
    const float* bout = (const float*)d_in[3];   // [256]
    float* out = (float*)d_out;                  // [131072,256]

    cudaFuncSetAttribute(fused_attn_kernel,
                         cudaFuncAttributeMaxDynamicSharedMemorySize, SM_BYTES);
    fused_attn_kernel<<<GROUPS, 256, SM_BYTES>>>(x, Wqkv, Wout, bout, out);
}

// round 6
// speedup vs baseline: 9.9101x; 1.1152x over previous
#include <cuda_runtime.h>
#include <cstdint>

constexpr int TOK = 32, DMODEL = 256, HEADS = 8, INNER = 512;
constexpr int GROUPS = 4096, NQKV = 1536, DHEAD = 64;

// ---- smem plan (float offsets) ----
// A-side arrays (LDSM): stride%32==4, 16B-aligned rows.
// B-side arrays (scalar): stride%32==8.
constexpr int XS_STR = 260, XS_OFF = 0;                    // x tf32 [32][256]
constexpr int WS_OFF = XS_OFF + 32 * XS_STR;               // W dbl-buf: 2 slots x 3200
constexpr int WS_STR = 200;                                //   B1: [16k][192] fp32 raw
constexpr int WO_STR = 264;                                //   B3: [8k][256] fp32 raw
constexpr int WSLOT  = 3200;
constexpr int QS_STR = 68,  QS_OFF = WS_OFF + 2 * WSLOT;   // Q tf32 [32][64]
constexpr int KS_STR = 68,  KS_OFF = QS_OFF + 32 * QS_STR; // K tf32 [32][64]
constexpr int VS_STR = 72,  VS_OFF = KS_OFF + 32 * KS_STR; // V tf32 [32][64]
constexpr int PS_STR = 36,  PS_OFF = VS_OFF + 32 * VS_STR; // P tf32 [32][32]
constexpr int AS_STR = 68,  AS_OFF = PS_OFF + 32 * PS_STR; // A tf32 [32][64]
constexpr int SM_FLOATS = AS_OFF + 32 * AS_STR;            // 24704 floats
constexpr int SM_BYTES  = SM_FLOATS * 4;                   // ~96.5 KB -> 2 blocks/SM

__device__ __forceinline__ float ftf(float f) {
    uint32_t u; asm("cvt.rna.tf32.f32 %0, %1;" : "=r"(u) : "f"(f));
    return __uint_as_float(u);
}
__device__ __forceinline__ uint32_t ftfu(float f) {
    uint32_t u; asm("cvt.rna.tf32.f32 %0, %1;" : "=r"(u) : "f"(f));
    return u;
}
__device__ __forceinline__ void mma8(float* d, const uint32_t* a, const uint32_t* b) {
    asm volatile("mma.sync.aligned.m16n8k8.row.col.f32.tf32.tf32.f32 "
                 "{%0,%1,%2,%3},{%4,%5,%6,%7},{%8,%9},{%0,%1,%2,%3};"
                 : "+f"(d[0]), "+f"(d[1]), "+f"(d[2]), "+f"(d[3])
                 : "r"(a[0]), "r"(a[1]), "r"(a[2]), "r"(a[3]), "r"(b[0]), "r"(b[1]));
}
__device__ __forceinline__ void ldsm4(uint32_t* r, uint32_t saddr) {
    asm volatile("ldmatrix.sync.aligned.m8n8.x4.shared.b16 {%0,%1,%2,%3}, [%4];"
                 : "=r"(r[0]), "=r"(r[1]), "=r"(r[2]), "=r"(r[3]) : "r"(saddr));
}
__device__ __forceinline__ void cpa16(uint32_t dst, const void* src) {
    asm volatile("cp.async.ca.shared.global [%0], [%1], 16;" :: "r"(dst), "l"(src));
}
__device__ __forceinline__ void cp_commit() { asm volatile("cp.async.commit_group;"); }
template<int N> __device__ __forceinline__ void cp_wait() {
    asm volatile("cp.async.wait_group %0;" :: "n"(N));
}

__global__ __launch_bounds__(256, 2)
void fused_attn_kernel(const float* __restrict__ x,
                       const float* __restrict__ Wqkv,
                       const float* __restrict__ Wout,
                       const float* __restrict__ bout,
                       float* __restrict__ out)
{
    extern __shared__ float sm[];
    const int tid = threadIdx.x;
    const int g   = blockIdx.x;
    const int w   = tid >> 5;
    const int ln  = tid & 31;
    const int g4  = ln >> 2;
    const int t4  = ln & 3;

    const uint32_t sb = (uint32_t)__cvta_generic_to_shared(sm);
    const int lrow = ln & 15, lcol4 = (ln >> 4) * 4;
    const uint32_t xs_lds = sb + ((XS_OFF + lrow * XS_STR + lcol4) << 2);
    const uint32_t qs_lds = sb + ((QS_OFF + ((w >> 2) * 16 + lrow) * QS_STR + lcol4) << 2);
    const uint32_t ps_lds = sb + ((PS_OFF + lrow * PS_STR + lcol4) << 2);
    const uint32_t as_lds = sb + ((AS_OFF + lrow * AS_STR + lcol4) << 2);

    // --- staging index precompute ---
    int wkk[3], wcol[3];               // B1 W chunk: 768 float4 / 256 thr
    #pragma unroll
    for (int it = 0; it < 3; it++) {
        int l = tid + it * 256;
        wkk[it] = l / 48; wcol[it] = (l % 48) * 4;
    }
    int odd8[2], oc4[2];               // B3 Wout chunk: 512 float4 / 256 thr
    #pragma unroll
    for (int it = 0; it < 2; it++) {
        int l = tid + it * 256;
        odd8[it] = l >> 6; oc4[it] = (l & 63) * 4;
    }

    auto issueW = [&](int h, int c, int p) {
        const int kc = c * 16;
        #pragma unroll
        for (int it = 0; it < 3; it++) {
            const int col = wcol[it], sec = col >> 6, dd = col & 63;
            cpa16(sb + ((WS_OFF + p * WSLOT + wkk[it] * WS_STR + col) << 2),
                  Wqkv + (size_t)(kc + wkk[it]) * NQKV + sec * INNER + h * DHEAD + dd);
        }
        cp_commit();
    };
    auto issueWO = [&](int h, int c, int p) {
        const int dc = c * 8;
        #pragma unroll
        for (int it = 0; it < 2; it++) {
            cpa16(sb + ((WS_OFF + p * WSLOT + odd8[it] * WO_STR + oc4[it]) << 2),
                  Wout + (size_t)(h * DHEAD + dc + odd8[it]) * DMODEL + oc4[it]);
        }
        cp_commit();
    };

    // prefetch first W chunk, then stage x (overlapped)
    issueW(0, 0, 0);
    {
        const float4* xg = reinterpret_cast<const float4*>(x + (size_t)g * TOK * DMODEL);
        #pragma unroll
        for (int it = 0; it < 8; it++) {
            int l = tid + it * 256;
            int row = l >> 6, c4 = l & 63;
            float4 v = xg[l];
            *reinterpret_cast<float4*>(sm + XS_OFF + row * XS_STR + c4 * 4) =
                make_float4(ftf(v.x), ftf(v.y), ftf(v.z), ftf(v.w));
        }
    }
    // out accumulators (bias preloaded)
    float o[2][4][4];
    #pragma unroll
    for (int nt = 0; nt < 4; nt++) {
        float b0 = bout[w * 32 + nt * 8 + 2 * t4];
        float b1 = bout[w * 32 + nt * 8 + 2 * t4 + 1];
        #pragma unroll
        for (int mt = 0; mt < 2; mt++) {
            o[mt][nt][0] = b0; o[mt][nt][1] = b1;
            o[mt][nt][2] = b0; o[mt][nt][3] = b1;
        }
    }

    for (int h = 0; h < HEADS; h++) {
        // ===== B1: QKV for head h (chunk0 already in flight) =====
        float d1[3][2][4] = {};
        #pragma unroll 1
        for (int c = 0; c < 16; c++) {
            if (c < 15) { issueW(h, c + 1, (c + 1) & 1); cp_wait<1>(); }
            else        { cp_wait<0>(); }
            __syncthreads();
            const float* wb = sm + WS_OFF + (c & 1) * WSLOT;
            const int kc = c * 16;
            #pragma unroll
            for (int ks = 0; ks < 2; ks++) {
                uint32_t a0[4], a1[4];
                ldsm4(a0, xs_lds + ((kc + ks * 8) << 2));
                ldsm4(a1, xs_lds + ((16 * XS_STR + kc + ks * 8) << 2));
                const float* wr = wb + ks * 8 * WS_STR + (w << 3) + g4;
                #pragma unroll
                for (int m = 0; m < 3; m++) {
                    const float* wc = wr + m * 64;
                    uint32_t b[2] = { ftfu(wc[t4 * WS_STR]), ftfu(wc[(t4 + 4) * WS_STR]) };
                    mma8(d1[m][0], a0, b);
                    mma8(d1[m][1], a1, b);
                }
            }
            __syncthreads();
        }
        // write Q/K/V (tf32)
        {
            const int cc = w * 8 + 2 * t4;
            #pragma unroll
            for (int m = 0; m < 3; m++) {
                float* dst = sm + (m == 0 ? QS_OFF : m == 1 ? KS_OFF : VS_OFF);
                const int str = (m == 2) ? VS_STR : QS_STR;
                #pragma unroll
                for (int mt = 0; mt < 2; mt++) {
                    int r0 = mt * 16 + g4;
                    dst[r0 * str + cc]           = ftf(d1[m][mt][0]);
                    dst[r0 * str + cc + 1]       = ftf(d1[m][mt][1]);
                    dst[(r0 + 8) * str + cc]     = ftf(d1[m][mt][2]);
                    dst[(r0 + 8) * str + cc + 1] = ftf(d1[m][mt][3]);
                }
            }
        }
        __syncthreads();

        // ===== B2a: S = Q K^T * scale =====
        {
            const int mt = w >> 2, nt = w & 3;
            float s[4] = {};
            #pragma unroll
            for (int ks = 0; ks < 8; ks++) {
                uint32_t a[4];
                ldsm4(a, qs_lds + ((ks * 8) << 2));
                const float* kb = sm + KS_OFF + (nt * 8 + g4) * KS_STR + ks * 8;
                uint32_t b[2] = { __float_as_uint(kb[t4]), __float_as_uint(kb[t4 + 4]) };
                mma8(s, a, b);
            }
            const int r0 = mt * 16 + g4, cc = nt * 8 + 2 * t4;
            sm[PS_OFF + r0 * PS_STR + cc]           = s[0] * 0.125f;
            sm[PS_OFF + r0 * PS_STR + cc + 1]       = s[1] * 0.125f;
            sm[PS_OFF + (r0 + 8) * PS_STR + cc]     = s[2] * 0.125f;
            sm[PS_OFF + (r0 + 8) * PS_STR + cc + 1] = s[3] * 0.125f;
        }
        __syncthreads();

        // ===== B2b: softmax rows =====
        {
            const int i8 = tid >> 3, cb = tid & 7;
            float sv[4];
            #pragma unroll
            for (int jj = 0; jj < 4; jj++) sv[jj] = sm[PS_OFF + i8 * PS_STR + cb + jj * 8];
            float mx = fmaxf(fmaxf(sv[0], sv[1]), fmaxf(sv[2], sv[3]));
            #pragma unroll
            for (int msk = 1; msk < 8; msk <<= 1)
                mx = fmaxf(mx, __shfl_xor_sync(0xffffffffu, mx, msk));
            float sum = 0.f;
            #pragma unroll
            for (int jj = 0; jj < 4; jj++) { sv[jj] = __expf(sv[jj] - mx); sum += sv[jj]; }
            #pragma unroll
            for (int msk = 1; msk < 8; msk <<= 1)
                sum += __shfl_xor_sync(0xffffffffu, sum, msk);
            const float inv = 1.f / sum;
            #pragma unroll
            for (int jj = 0; jj < 4; jj++)
                sm[PS_OFF + i8 * PS_STR + cb + jj * 8] = ftf(sv[jj] * inv);
        }
        __syncthreads();
        issueWO(h, 0, 0);    // prefetch first Wout chunk during B2c

        // ===== B2c: A = P V =====
        {
            float dpv[2][4] = {};
            #pragma unroll
            for (int ks = 0; ks < 4; ks++) {
                const float* vb = sm + VS_OFF + ks * 8 * VS_STR + (w << 3) + g4;
                uint32_t b[2] = { __float_as_uint(vb[t4 * VS_STR]),
                                  __float_as_uint(vb[(t4 + 4) * VS_STR]) };
                uint32_t a0[4], a1[4];
                ldsm4(a0, ps_lds + ((ks * 8) << 2));
                ldsm4(a1, ps_lds + ((16 * PS_STR + ks * 8) << 2));
                mma8(dpv[0], a0, b);
                mma8(dpv[1], a1, b);
            }
            const int cc = w * 8 + 2 * t4;
            #pragma unroll
            for (int mt = 0; mt < 2; mt++) {
                int r0 = mt * 16 + g4;
                sm[AS_OFF + r0 * AS_STR + cc]           = ftf(dpv[mt][0]);
                sm[AS_OFF + r0 * AS_STR + cc + 1]       = ftf(dpv[mt][1]);
                sm[AS_OFF + (r0 + 8) * AS_STR + cc]     = ftf(dpv[mt][2]);
                sm[AS_OFF + (r0 + 8) * AS_STR + cc + 1] = ftf(dpv[mt][3]);
            }
        }
        __syncthreads();

        // ===== B3: out += A_h @ Wout[h*64:(h+1)*64] =====
        #pragma unroll 1
        for (int c = 0; c < 8; c++) {
            if (c < 7) { issueWO(h, c + 1, (c + 1) & 1); cp_wait<1>(); }
            else       { cp_wait<0>(); }
            __syncthreads();
            const int dc = c * 8;
            uint32_t a0[4], a1[4];
            ldsm4(a0, as_lds + (dc << 2));
            ldsm4(a1, as_lds + ((16 * AS_STR + dc) << 2));
            const float* wo = sm + WS_OFF + (c & 1) * WSLOT + (w << 5) + g4;
            #pragma unroll
            for (int nt = 0; nt < 4; nt++) {
                const float* wc = wo + nt * 8;
                uint32_t b[2] = { ftfu(wc[t4 * WO_STR]), ftfu(wc[(t4 + 4) * WO_STR]) };
                mma8(o[0][nt], a0, b);
                mma8(o[1][nt], a1, b);
            }
            __syncthreads();
        }
        if (h < 7) issueW(h + 1, 0, 0);   // prefetch next head's first W chunk
    }

    // ---- store ----
    #pragma unroll
    for (int mt = 0; mt < 2; mt++)
        #pragma unroll
        for (int nt = 0; nt < 4; nt++) {
            const int r0 = mt * 16 + g4, cc = w * 32 + nt * 8 + 2 * t4;
            float* p0 = out + ((size_t)g * TOK + r0) * DMODEL + cc;
            float* p1 = out + ((size_t)g * TOK + r0 + 8) * DMODEL + cc;
            *reinterpret_cast<float2*>(p0) = make_float2(o[mt][nt][0], o[mt][nt][1]);
            *reinterpret_cast<float2*>(p1) = make_float2(o[mt][nt][2], o[mt][nt][3]);
        }
}

extern "C" void kernel_launch(void* const* d_in, const int* in_sizes, int n_in,
                              void* d_out, int out_size)
{
    const float* x    = (const float*)d_in[0];   // [4,1024,32,256]
    const float* Wqkv = (const float*)d_in[1];   // [256,1536]
    const float* Wout = (const float*)d_in[2];   // [512,256]
    const float* bout = (const float*)d_in[3];   // [256]
    float* out = (float*)d_out;                  // [131072,256]

    cudaFuncSetAttribute(fused_attn_kernel,
                         cudaFuncAttributeMaxDynamicSharedMemorySize, SM_BYTES);
    fused_attn_kernel<<<GROUPS, 256, SM_BYTES>>>(x, Wqkv, Wout, bout, out);
}